// round 15
// baseline (speedup 1.0000x reference)
#include <cuda_runtime.h>
#include <cuda_fp16.h>
#include <cstdint>

#define NSYMS  256
#define NSTEPS 8192
#define NCH    62
#define HID    16

// ===========================================================================
// fp16 B fragments for mma.m16n8k16 (market cols only; k=62,63 zeroed):
//   g_Bfrag16[(ks*8+nt)*32 + lane] = { h01, h89 }
// g_Wst[0..63] = W_eff[o][sym], g_Wst[64..127] = W_eff[o][t]  (fp32, exact)
// ===========================================================================
__device__ uint2 g_Bfrag16[4 * 8 * 32];
__device__ float g_Wst[128];

__global__ void build_weff(const float* __restrict__ W1h, const float* __restrict__ M1h,
                           const float* __restrict__ W2h, const float* __restrict__ M2h,
                           const float* __restrict__ W3h, const float* __restrict__ M3h) {
    __shared__ float W1[HID * 64];
    __shared__ float W2[HID * HID];
    __shared__ float W3[64 * HID];
    __shared__ float T2[HID * 64];
    __shared__ float Wt[64 * 64];   // [cin][o]
    const int tid = threadIdx.x;

    for (int i = tid; i < HID * 64; i += 256)
        W1[i] = tanhf(W1h[i]) * (1.0f / (1.0f + expf(-M1h[i])));
    for (int i = tid; i < HID * HID; i += 256)
        W2[i] = tanhf(W2h[i]) * (1.0f / (1.0f + expf(-M2h[i])));
    for (int i = tid; i < 64 * HID; i += 256)
        W3[i] = tanhf(W3h[i]) * (1.0f / (1.0f + expf(-M3h[i])));
    __syncthreads();

    for (int i = tid; i < HID * 64; i += 256) {
        int h = i >> 6, c = i & 63;
        float s = 0.0f;
#pragma unroll
        for (int k = 0; k < HID; k++) s += W2[h * HID + k] * W1[k * 64 + c];
        T2[i] = s;
    }
    __syncthreads();

    for (int i = tid; i < 64 * 64; i += 256) {
        int o = i >> 6, c = i & 63;
        float s = 0.0f;
#pragma unroll
        for (int k = 0; k < HID; k++) s += W3[o * HID + k] * T2[k * 64 + c];
        Wt[c * 64 + o] = s;
    }
    __syncthreads();

    for (int i = tid; i < 1024; i += 256) {
        int lane = i & 31, nt = (i >> 5) & 7, ks = i >> 8;
        int g = lane >> 2, q = lane & 3;
        int n = nt * 8 + g;
        int k0 = ks * 16 + 2 * q;
        float w[4];
#pragma unroll
        for (int j = 0; j < 4; j++) {
            int k = k0 + (j >> 1) * 8 + (j & 1);
            w[j] = (k < 62) ? Wt[(k + 2) * 64 + n] : 0.0f;
        }
        __half2 h01 = __floats2half2_rn(w[0], w[1]);
        __half2 h89 = __floats2half2_rn(w[2], w[3]);
        uint2 u;
        u.x = *reinterpret_cast<uint32_t*>(&h01);
        u.y = *reinterpret_cast<uint32_t*>(&h89);
        g_Bfrag16[i] = u;
    }
    for (int i = tid; i < 128; i += 256)
        g_Wst[i] = Wt[i];
}

// ===========================================================================
// PTX helpers
// ===========================================================================
__device__ __forceinline__ void mma16816h(float& d0, float& d1, float& d2, float& d3,
                                          uint32_t a0, uint32_t a1, uint32_t a2, uint32_t a3,
                                          uint32_t b0, uint32_t b1) {
    asm volatile("mma.sync.aligned.m16n8k16.row.col.f32.f16.f16.f32 "
                 "{%0,%1,%2,%3}, {%4,%5,%6,%7}, {%8,%9}, {%0,%1,%2,%3};"
                 : "+f"(d0), "+f"(d1), "+f"(d2), "+f"(d3)
                 : "r"(a0), "r"(a1), "r"(a2), "r"(a3), "r"(b0), "r"(b1));
}
__device__ __forceinline__ void cvt_split_h(float x, float y, uint32_t& h, uint32_t& l) {
    __half2 h2 = __floats2half2_rn(x, y);
    float2 hf = __half22float2(h2);
    __half2 l2 = __floats2half2_rn(x - hf.x, y - hf.y);
    h = *reinterpret_cast<uint32_t*>(&h2);
    l = *reinterpret_cast<uint32_t*>(&l2);
}
__device__ __forceinline__ uint32_t smem_u32(const void* p) {
    uint32_t a;
    asm("{ .reg .u64 t; cvta.to.shared.u64 t, %1; cvt.u32.u64 %0, t; }" : "=r"(a) : "l"(p));
    return a;
}
#define STS64F(a, f0, f1) \
    asm volatile("st.shared.v2.f32 [%0], {%1, %2};" :: "r"(a), "f"(f0), "f"(f1) : "memory")
#define LDS128F(f0, f1, f2, f3, a) \
    asm volatile("ld.shared.v4.f32 {%0, %1, %2, %3}, [%4];" : "=f"(f0), "=f"(f1), "=f"(f2), "=f"(f3) : "r"(a))

// ===========================================================================
// Main kernel: K-split warp pairs, 16 warps, ~110 regs (no spill).
//   CTA: 512 thr = 8 pairs; pair p owns rows [p*16, p*16+16) of each slab;
//   warp h of the pair owns k-slices {2h, 2h+1} (input cols 32h..32h+31).
//   Partial accs reduced through the pair's two 4KB epilogue half-tiles.
//   128 rows/iter, ITERS=8 -> 1024 rows/CTA; grid 2048.
// ===========================================================================
#define ITERS 8
#define TPB   512
#define SM_EPI_BYTES (8 * 8192)               // 8 pairs x (2 x 4KB half-tiles)
#define SM_TOTAL     (SM_EPI_BYTES + 512)

__global__ void __launch_bounds__(TPB, 1)
encode_kernel(const float* __restrict__ market, float* __restrict__ out) {
    extern __shared__ char smem[];
    float* scorr = (float*)(smem + SM_EPI_BYTES);   // [0..63] s*Wsym, [64..127] Wt

    const int tid  = threadIdx.x;
    const int warp = tid >> 5;
    const int lane = tid & 31;
    const int g = lane >> 2;     // 0..7
    const int q = lane & 3;      // 0..3
    const int pair = warp >> 1;  // 0..7
    const int h    = warp & 1;   // k-half

    // ---- B fragments for this k-half only: 32 regs
    uint32_t BH0[16], BH1[16];
#pragma unroll
    for (int ksl = 0; ksl < 2; ksl++)
#pragma unroll
        for (int nt = 0; nt < 8; nt++) {
            uint2 u = g_Bfrag16[((h * 2 + ksl) * 8 + nt) * 32 + lane];
            BH0[ksl * 8 + nt] = u.x;
            BH1[ksl * 8 + nt] = u.y;
        }

    const long long cta_row0 = (long long)blockIdx.x * (128 * ITERS);  // 1024-aligned
    const float sval = (float)(cta_row0 >> 13);
    const int   tcta = (int)(cta_row0 & (NSTEPS - 1));

    if (tid < 64) {
        scorr[tid]      = sval * g_Wst[tid];
        scorr[64 + tid] = g_Wst[64 + tid];
    }
    __syncthreads();

    const uint32_t ptile = smem_u32(smem) + pair * 8192;   // pair tile (2 halves)
    const uint32_t wb = ptile + h * 4096;                  // this warp's half

#pragma unroll 1
    for (int it = 0; it < ITERS; it++) {
        const int rloc = it * 128 + pair * 16 + g;
        const float* p0 = market + (cta_row0 + rloc) * NCH;
        const float* p1 = p0 + 8 * NCH;

        // ---- loads: this warp's 2 k-slices (8 x LDG.64, each element once)
        float2 vc[8];   // [ksl*4 + {p0 pair0, p0 pair1, p1 pair0, p1 pair1}]
#pragma unroll
        for (int ksl = 0; ksl < 2; ksl++) {
            const int c0 = (h * 2 + ksl) * 16 + 2 * q;
            vc[ksl * 4 + 0] = *(const float2*)(p0 + c0);
            vc[ksl * 4 + 2] = *(const float2*)(p1 + c0);
            if (h == 1 && ksl == 1 && q == 3) {
                vc[5] = make_float2(0.0f, 0.0f);   // cols 62,63: exact affine below
                vc[7] = make_float2(0.0f, 0.0f);
            } else {
                vc[ksl * 4 + 1] = *(const float2*)(p0 + c0 + 8);
                vc[ksl * 4 + 3] = *(const float2*)(p1 + c0 + 8);
            }
        }

        // ---- convert + MMA (partial K): D_h = (Ah + Al) * Bh over 2 k-slices
        float acc[32];
#pragma unroll
        for (int i = 0; i < 32; i++) acc[i] = 0.0f;

#pragma unroll
        for (int ksl = 0; ksl < 2; ksl++) {
            uint32_t ah0, ah1, ah2, ah3, al0, al1, al2, al3;
            cvt_split_h(vc[ksl*4+0].x, vc[ksl*4+0].y, ah0, al0);   // row g,   pair0
            cvt_split_h(vc[ksl*4+2].x, vc[ksl*4+2].y, ah1, al1);   // row g+8, pair0
            cvt_split_h(vc[ksl*4+1].x, vc[ksl*4+1].y, ah2, al2);   // row g,   pair1
            cvt_split_h(vc[ksl*4+3].x, vc[ksl*4+3].y, ah3, al3);   // row g+8, pair1
#pragma unroll
            for (int nt = 0; nt < 8; nt++) {
                const int bi = ksl * 8 + nt;
                mma16816h(acc[nt*4+0], acc[nt*4+1], acc[nt*4+2], acc[nt*4+3],
                          ah0, ah1, ah2, ah3, BH0[bi], BH1[bi]);
                mma16816h(acc[nt*4+0], acc[nt*4+1], acc[nt*4+2], acc[nt*4+3],
                          al0, al1, al2, al3, BH0[bi], BH1[bi]);
            }
        }

        // ---- partial fragments -> this warp's swizzled half-tile
        {
            const int qhi = q >> 1, qlo = q & 1;
#pragma unroll
            for (int nt = 0; nt < 8; nt++) {
                uint32_t f4a = (uint32_t)((2 * nt + qhi) ^ g);
                uint32_t f4b = (uint32_t)((2 * nt + qhi) ^ (g + 8));
                STS64F(wb + g * 256 + f4a * 16 + qlo * 8,       acc[nt*4+0], acc[nt*4+1]);
                STS64F(wb + (g + 8) * 256 + f4b * 16 + qlo * 8, acc[nt*4+2], acc[nt*4+3]);
            }
        }
        __syncthreads();   // both halves of every pair tile complete

        // ---- reduce halves + exact affine + coalesced STG (warp h: rows 8h..8h+8)
        {
            float* obase = out + (cta_row0 + (long long)it * 128 + pair * 16) * 64;
            const float tbase = (float)(tcta + it * 128 + pair * 16);
#pragma unroll
            for (int i = 0; i < 4; i++) {
                int slot = (h * 4 + i) * 32 + lane;
                int row = slot >> 4;            // 8h .. 8h+7
                int c4 = slot & 15;
                uint32_t off = (uint32_t)(row * 256 + ((c4 ^ row) << 4));
                float a0, a1, a2, a3, b0, b1, b2, b3;
                LDS128F(a0, a1, a2, a3, ptile + off);           // half 0
                LDS128F(b0, b1, b2, b3, ptile + 4096 + off);    // half 1
                float4 cr = *(const float4*)(scorr + c4 * 4);
                float4 wt = *(const float4*)(scorr + 64 + c4 * 4);
                float tv = tbase + (float)row;
                a0 += b0 + cr.x + tv * wt.x;
                a1 += b1 + cr.y + tv * wt.y;
                a2 += b2 + cr.z + tv * wt.z;
                a3 += b3 + cr.w + tv * wt.w;
                *(float4*)(obase + row * 64 + c4 * 4) = make_float4(a0, a1, a2, a3);
            }
        }
        __syncthreads();   // reads done before next iter overwrites tiles
    }
}

// ---------------------------------------------------------------------------
extern "C" void kernel_launch(void* const* d_in, const int* in_sizes, int n_in,
                              void* d_out, int out_size) {
    const float* market = (const float*)d_in[0];
    build_weff<<<1, 256>>>((const float*)d_in[1], (const float*)d_in[2],
                           (const float*)d_in[3], (const float*)d_in[4],
                           (const float*)d_in[5], (const float*)d_in[6]);

    cudaFuncSetAttribute((const void*)encode_kernel,
                         cudaFuncAttributeMaxDynamicSharedMemorySize, SM_TOTAL);
    const int nblocks = (NSYMS * NSTEPS) / (128 * ITERS);   // 2048
    encode_kernel<<<nblocks, TPB, SM_TOTAL>>>(market, (float*)d_out);
}